// round 17
// baseline (speedup 1.0000x reference)
#include <cuda_runtime.h>
#include <math.h>
#include <stdint.h>

#define D_MODEL 1024
#define NH      16
#define HD      64
#define B_      2
#define T_      2048
#define BT      4096
#define BH      32

// ------------------------- device scratch (no allocs) ----------------------
__device__ float g_q  [BH * T_ * HD];      // [bh][t][dd]   (tf32)
__device__ float g_k  [BH * T_ * HD];      // [bh][s][dd]   (tf32)
__device__ float g_v  [BH * T_ * HD];      // [bh][t][dd]   (exact)
__device__ float g_vt [BH * HD * T_];      // [bh][dd][t]   (tf32)
__device__ float g_ao [BT * D_MODEL];      // [b*t][D]      (tf32)
__device__ float g_wt [3 * D_MODEL * D_MODEL];   // Wqkv^T (tf32)
__device__ float g_wot[D_MODEL * D_MODEL];       // Wo^T   (tf32)
__device__ float g_rowsum[BH * T_];

// ------------------------------ helpers ------------------------------------
__device__ __forceinline__ uint32_t s2u(const void* p) {
    return (uint32_t)__cvta_generic_to_shared(p);
}
__device__ __forceinline__ void cpa16(uint32_t d, const void* g) {
    asm volatile("cp.async.cg.shared.global [%0], [%1], 16;" :: "r"(d), "l"(g));
}
__device__ __forceinline__ void cpcommit() { asm volatile("cp.async.commit_group;"); }
template <int N> __device__ __forceinline__ void cpwait() {
    asm volatile("cp.async.wait_group %0;" :: "n"(N));
}
__device__ __forceinline__ float f2tf(float f) {
    uint32_t r; asm("cvt.rna.tf32.f32 %0, %1;" : "=r"(r) : "f"(f));
    return __uint_as_float(r);
}
__device__ __forceinline__ void mma8(float* c, const uint32_t* a, const uint32_t* b) {
    asm volatile("mma.sync.aligned.m16n8k8.row.col.f32.tf32.tf32.f32 "
        "{%0,%1,%2,%3}, {%4,%5,%6,%7}, {%8,%9}, {%0,%1,%2,%3};"
        : "+f"(c[0]), "+f"(c[1]), "+f"(c[2]), "+f"(c[3])
        : "r"(a[0]), "r"(a[1]), "r"(a[2]), "r"(a[3]), "r"(b[0]), "r"(b[1]));
}
__device__ __forceinline__ void ldsm4(uint32_t& r0, uint32_t& r1,
                                      uint32_t& r2, uint32_t& r3, uint32_t addr) {
    asm volatile("ldmatrix.sync.aligned.m8n8.x4.shared.b16 {%0,%1,%2,%3}, [%4];"
        : "=r"(r0), "=r"(r1), "=r"(r2), "=r"(r3) : "r"(addr));
}

// ======================= prep kernels =======================================
__global__ void transpose_w2(const float* __restrict__ Wqkv,
                             const float* __restrict__ Wo,
                             float* __restrict__ outq, float* __restrict__ outo) {
    __shared__ float tb[32][33];
    int z = blockIdx.z;
    const float* in; float* out; int R = 1024, C;
    if (z == 0) { in = Wqkv; out = outq; C = 3072; }
    else        { in = Wo;   out = outo; C = 1024; }
    int bx = blockIdx.x * 32, by = blockIdx.y * 32;
    if (bx >= C) return;
    int x = bx + threadIdx.x;
    #pragma unroll
    for (int i = threadIdx.y; i < 32; i += 8)
        tb[i][threadIdx.x] = in[(size_t)(by + i) * C + x];
    __syncthreads();
    int x2 = by + threadIdx.x;
    #pragma unroll
    for (int i = threadIdx.y; i < 32; i += 8)
        out[(size_t)(bx + i) * R + x2] = f2tf(tb[threadIdx.x][i]);
}

__global__ void transpose_v() {
    __shared__ float tb[32][33];
    int bh = blockIdx.z;
    const float* in = g_v + (size_t)bh * T_ * HD;
    float* out = g_vt + (size_t)bh * HD * T_;
    int bx = blockIdx.x * 32, by = blockIdx.y * 32;
    int x = bx + threadIdx.x;
    #pragma unroll
    for (int i = threadIdx.y; i < 32; i += 8)
        tb[i][threadIdx.x] = in[(size_t)(by + i) * HD + x];
    __syncthreads();
    int x2 = by + threadIdx.x;
    #pragma unroll
    for (int i = threadIdx.y; i < 32; i += 8)
        out[(size_t)(bx + i) * T_ + x2] = f2tf(tb[threadIdx.x][i]);
}

// ======================= big projection GEMM (R14/R16) ======================
#define GBS 36
template <int MODE>
__global__ void __launch_bounds__(256, 2)
gemm_big(const float* __restrict__ A, const float* __restrict__ Bt,
         const float* __restrict__ bias, float* __restrict__ Cout) {
    extern __shared__ float sm[];
    float (*As)[128][GBS] = (float(*)[128][GBS])sm;
    float (*Bs)[128][GBS] = (float(*)[128][GBS])(sm + 3 * 128 * GBS);

    int tid = threadIdx.x, wid = tid >> 5, lane = tid & 31;
    int gr = lane >> 2, tq = lane & 3;
    int warpm = wid & 3, warpn = wid >> 2;
    int row0 = blockIdx.y * 128, col0 = blockIdx.x * 128;

    int g8 = lane >> 3, lr = lane & 7;
    int aro = (g8 & 1) * 8 + lr, aco = (g8 >> 1) * 4;
    int bro = (g8 >> 1) * 8 + lr, bco = (g8 & 1) * 4;

    float acc[2][8][4];
    #pragma unroll
    for (int i = 0; i < 2; i++)
        #pragma unroll
        for (int j = 0; j < 8; j++)
            #pragma unroll
            for (int q = 0; q < 4; q++) acc[i][j][q] = 0.f;

    auto load_stage = [&](int c) {
        int s = c % 3;
        #pragma unroll
        for (int p = 0; p < 4; p++) {
            int idx = tid + p * 256;
            int r = idx >> 3, c16 = idx & 7;
            cpa16(s2u(&As[s][r][c16 * 4]), &A[(size_t)(row0 + r) * 1024 + c * 32 + c16 * 4]);
            cpa16(s2u(&Bs[s][r][c16 * 4]), &Bt[(size_t)(col0 + r) * 1024 + c * 32 + c16 * 4]);
        }
        cpcommit();
    };

    auto mma_half = [&](int s, int k8base) {
        #pragma unroll
        for (int k8 = 0; k8 < 16; k8 += 8) {
            int kk = k8base + k8;
            uint32_t a[2][4];
            #pragma unroll
            for (int i = 0; i < 2; i++)
                ldsm4(a[i][0], a[i][1], a[i][2], a[i][3],
                      s2u(&As[s][warpm * 32 + i * 16 + aro][kk + aco]));
            #pragma unroll
            for (int jp = 0; jp < 4; jp++) {
                uint32_t b0, b1, b2, b3;
                ldsm4(b0, b1, b2, b3,
                      s2u(&Bs[s][warpn * 64 + jp * 16 + bro][kk + bco]));
                uint32_t bj0[2] = {b0, b1}, bj1[2] = {b2, b3};
                #pragma unroll
                for (int i = 0; i < 2; i++) {
                    mma8(acc[i][jp * 2 + 0], a[i], bj0);
                    mma8(acc[i][jp * 2 + 1], a[i], bj1);
                }
            }
        }
    };

    load_stage(0); load_stage(1);

    for (int c = 0; c < 32; c++) {
        int s = c % 3;
        if (c < 31) cpwait<1>(); else cpwait<0>();
        __syncthreads();

        mma_half(s, 0);
        if (c + 2 < 32) load_stage(c + 2);
        mma_half(s, 16);
    }

    #pragma unroll
    for (int i = 0; i < 2; i++) {
        #pragma unroll
        for (int half = 0; half < 2; half++) {
            int m = row0 + warpm * 32 + i * 16 + gr + half * 8;
            #pragma unroll
            for (int j = 0; j < 8; j++) {
                int col = col0 + warpn * 64 + j * 8 + 2 * tq;
                float v0 = acc[i][j][half * 2 + 0] + __ldg(&bias[col]);
                float v1 = acc[i][j][half * 2 + 1] + __ldg(&bias[col + 1]);
                if (MODE == 1) {
                    *(float2*)&Cout[(size_t)m * 1024 + col] = make_float2(v0, v1);
                } else {
                    int which = col >> 10;
                    int d = col & 1023, h = d >> 6, dd = d & 63;
                    int b = m >> 11, t = m & 2047;
                    if (which != 2) { v0 = f2tf(v0); v1 = f2tf(v1); }
                    float* dst = (which == 0) ? g_q : (which == 1) ? g_k : g_v;
                    *(float2*)&dst[((size_t)(b * NH + h) * T_ + t) * HD + dd] =
                        make_float2(v0, v1);
                }
            }
        }
    }
}

// ===== kernel A: QK^T once -> raw E to wts + rowsums (no atomics) ===========
#define ESS 132
#define SA_QS   0
#define SA_KS   (128 * 68)
#define SA_ES   (SA_KS + 2 * 128 * 68)
#define SA_PART (SA_ES + 128 * ESS)
#define SA_FLTS (SA_PART + 2 * 128)

__global__ void __launch_bounds__(256, 1) attn_scores_e(float* __restrict__ wts) {
    extern __shared__ float sm[];
    float* Qs   = sm + SA_QS;
    float* Ks   = sm + SA_KS;
    float* Es   = sm + SA_ES;
    float* part = sm + SA_PART;

    int tid = threadIdx.x, wid = tid >> 5, lane = tid & 31;
    int gr = lane >> 2, tq = lane & 3;
    int warpm = wid & 3, warpn = wid >> 2;
    int r0 = blockIdx.x * 128, bh = blockIdx.y;

    int g8 = lane >> 3, lr = lane & 7;
    int aro = (g8 & 1) * 8 + lr, aco = (g8 >> 1) * 4;
    int bro = (g8 >> 1) * 8 + lr, bco = (g8 & 1) * 4;

    const float* qh = g_q + ((size_t)bh * T_ + r0) * HD;
    const float* kh = g_k + (size_t)bh * T_ * HD;
    float* wbase = wts + ((size_t)bh * T_ + r0) * T_;

    auto loadK = [&](int c) {
        float* dst = Ks + (size_t)(c & 1) * 128 * 68;
        #pragma unroll
        for (int p = 0; p < 8; p++) {
            int idx = tid + p * 256;
            int r = idx >> 4, c4 = idx & 15;
            cpa16(s2u(&dst[r * 68 + c4 * 4]), kh + (size_t)(c * 128 + r) * HD + c4 * 4);
        }
        cpcommit();
    };

    #pragma unroll
    for (int p = 0; p < 8; p++) {
        int idx = tid + p * 256;
        int r = idx >> 4, c4 = idx & 15;
        cpa16(s2u(&Qs[r * 68 + c4 * 4]), qh + (size_t)r * HD + c4 * 4);
    }
    {
        float* dst = Ks;
        #pragma unroll
        for (int p = 0; p < 8; p++) {
            int idx = tid + p * 256;
            int r = idx >> 4, c4 = idx & 15;
            cpa16(s2u(&dst[r * 68 + c4 * 4]), kh + (size_t)r * HD + c4 * 4);
        }
    }
    cpcommit();
    loadK(1);

    float sums[2][2] = {{0.f, 0.f}, {0.f, 0.f}};

    for (int c = 0; c < 16; c++) {
        if (c < 15) cpwait<1>(); else cpwait<0>();
        __syncthreads();
        const float* Kb = Ks + (size_t)(c & 1) * 128 * 68;

        float acc[2][8][4];
        #pragma unroll
        for (int i = 0; i < 2; i++)
            #pragma unroll
            for (int j = 0; j < 8; j++)
                #pragma unroll
                for (int q = 0; q < 4; q++) acc[i][j][q] = 0.f;

        #pragma unroll
        for (int k8 = 0; k8 < 64; k8 += 8) {
            uint32_t a[2][4];
            #pragma unroll
            for (int i = 0; i < 2; i++)
                ldsm4(a[i][0], a[i][1], a[i][2], a[i][3],
                      s2u(&Qs[(warpm * 32 + i * 16 + aro) * 68 + k8 + aco]));
            #pragma unroll
            for (int jp = 0; jp < 4; jp++) {
                uint32_t b0, b1, b2, b3;
                ldsm4(b0, b1, b2, b3,
                      s2u(&Kb[(warpn * 64 + jp * 16 + bro) * 68 + k8 + bco]));
                uint32_t bj0[2] = {b0, b1}, bj1[2] = {b2, b3};
                #pragma unroll
                for (int i = 0; i < 2; i++) {
                    mma8(acc[i][jp * 2 + 0], a[i], bj0);
                    mma8(acc[i][jp * 2 + 1], a[i], bj1);
                }
            }
        }

        // E = exp(score/8) -> Es staging (+ rowsum partials in registers)
        #pragma unroll
        for (int i = 0; i < 2; i++) {
            #pragma unroll
            for (int half = 0; half < 2; half++) {
                int lrw = warpm * 32 + i * 16 + gr + half * 8;
                float s = 0.f;
                #pragma unroll
                for (int j = 0; j < 8; j++) {
                    int col = warpn * 64 + j * 8 + 2 * tq;
                    float e0 = __expf(0.125f * acc[i][j][half * 2 + 0]);
                    float e1 = __expf(0.125f * acc[i][j][half * 2 + 1]);
                    s += e0 + e1;
                    *(float2*)&Es[lrw * ESS + col] = make_float2(e0, e1);
                }
                sums[i][half] += s;
            }
        }
        __syncthreads();   // Es complete (and Ks buffer consumed)

        // coalesced raw-E store
        #pragma unroll
        for (int rr = 0; rr < 16; rr++) {
            int row = wid * 16 + rr;
            float4 v = *(float4*)&Es[row * ESS + lane * 4];
            *(float4*)&wbase[(size_t)row * T_ + c * 128 + lane * 4] = v;
        }
        if (c + 2 < 16) loadK(c + 2);
    }

    // rowsums: tq-lane reduce -> smem partials (per warpn) -> direct store
    #pragma unroll
    for (int i = 0; i < 2; i++)
        #pragma unroll
        for (int half = 0; half < 2; half++) {
            float s = sums[i][half];
            s += __shfl_xor_sync(0xffffffffu, s, 1);
            s += __shfl_xor_sync(0xffffffffu, s, 2);
            if (tq == 0) {
                int r = warpm * 32 + i * 16 + gr + half * 8;
                part[warpn * 128 + r] = s;
            }
        }
    __syncthreads();
    if (tid < 128)
        g_rowsum[(size_t)bh * T_ + r0 + tid] = part[tid] + part[128 + tid];
}

// ===== kernel B: stream E, write W=E*inv, O = inv*(E @ V) ===================
// smem: Es[3][128][36] | Vs[3][64][36] | inv[128]  = ~83.5 KB -> occ 2
#define AV_ES   0
#define AV_VS   (3 * 128 * 36)
#define AV_INV  (AV_VS + 3 * 64 * 36)
#define AV_FLTS (AV_INV + 128)

__global__ void __launch_bounds__(256, 2) attn_av(float* __restrict__ wts) {
    extern __shared__ float sm[];
    float (*Es)[128][36] = (float(*)[128][36])(sm + AV_ES);
    float (*Vs)[64][36]  = (float(*)[64][36])(sm + AV_VS);
    float* inv = sm + AV_INV;

    int tid = threadIdx.x, wid = tid >> 5, lane = tid & 31;
    int gr = lane >> 2, tq = lane & 3;
    int warpm = wid & 3, warpn = wid >> 2;
    int r0 = blockIdx.x * 128, bh = blockIdx.y;

    int g8 = lane >> 3, lr = lane & 7;
    int aro = (g8 & 1) * 8 + lr, aco = (g8 >> 1) * 4;
    int bro = (g8 >> 1) * 8 + lr, bco = (g8 & 1) * 4;

    float* wbase = wts + ((size_t)bh * T_ + r0) * T_;
    const float* vtb = g_vt + (size_t)bh * HD * T_;

    if (tid < 128) inv[tid] = 1.f / g_rowsum[(size_t)bh * T_ + r0 + tid];

    auto load_stage = [&](int c) {
        int s = c % 3;
        #pragma unroll
        for (int p = 0; p < 4; p++) {          // E: 128 rows x 32 cols
            int idx = tid + p * 256;
            int r = idx >> 3, c16 = idx & 7;
            cpa16(s2u(&Es[s][r][c16 * 4]), &wbase[(size_t)r * T_ + c * 32 + c16 * 4]);
        }
        #pragma unroll
        for (int p = 0; p < 2; p++) {          // Vt: 64 rows x 32 cols
            int idx = tid + p * 256;
            int r = idx >> 3, c16 = idx & 7;
            cpa16(s2u(&Vs[s][r][c16 * 4]), vtb + (size_t)r * T_ + c * 32 + c16 * 4);
        }
        cpcommit();
    };

    load_stage(0); load_stage(1);

    float acco[2][4][4];
    #pragma unroll
    for (int i = 0; i < 2; i++)
        #pragma unroll
        for (int j = 0; j < 4; j++)
            #pragma unroll
            for (int q = 0; q < 4; q++) acco[i][j][q] = 0.f;

    for (int c = 0; c < 64; c++) {
        int s = c % 3;
        if (c < 63) cpwait<1>(); else cpwait<0>();
        __syncthreads();               // Es[s]/Vs[s] valid; inv ready

        // ---- W = E * inv, coalesced (4 rows x 32 cols per warp pass) ----
        #pragma unroll
        for (int pass = 0; pass < 4; pass++) {
            int row = wid * 16 + pass * 4 + (lane >> 3);
            int col = (lane & 7) * 4;
            float4 e = *(float4*)&Es[s][row][col];
            float iv = inv[row];
            e.x *= iv; e.y *= iv; e.z *= iv; e.w *= iv;
            *(float4*)&wbase[(size_t)row * T_ + c * 32 + col] = e;
        }

        // ---- PV on raw E ----
        #pragma unroll
        for (int k8 = 0; k8 < 32; k8 += 8) {
            uint32_t a[2][4];
            #pragma unroll
            for (int i = 0; i < 2; i++)
                ldsm4(a[i][0], a[i][1], a[i][2], a[i][3],
                      s2u(&Es[s][warpm * 32 + i * 16 + aro][k8 + aco]));
            #pragma unroll
            for (int jp = 0; jp < 2; jp++) {
                uint32_t b0, b1, b2, b3;
                ldsm4(b0, b1, b2, b3,
                      s2u(&Vs[s][warpn * 32 + jp * 16 + bro][k8 + bco]));
                uint32_t bj0[2] = {b0, b1}, bj1[2] = {b2, b3};
                #pragma unroll
                for (int i = 0; i < 2; i++) {
                    mma8(acco[i][jp * 2 + 0], a[i], bj0);
                    mma8(acco[i][jp * 2 + 1], a[i], bj1);
                }
            }
        }
        if (c + 2 < 64) load_stage(c + 2);
    }

    // ---- epilogue: O = inv * acco -> g_ao (tf32) ----
    int b = bh >> 4, h = bh & 15;
    #pragma unroll
    for (int i = 0; i < 2; i++) {
        #pragma unroll
        for (int half = 0; half < 2; half++) {
            int lrw = warpm * 32 + i * 16 + gr + half * 8;
            float iv = inv[lrw];
            int t = r0 + lrw;
            float* orow = g_ao + (size_t)(b * T_ + t) * D_MODEL + h * HD;
            #pragma unroll
            for (int j = 0; j < 4; j++) {
                int dd = warpn * 32 + j * 8 + 2 * tq;
                *(float2*)&orow[dd] = make_float2(
                    f2tf(acco[i][j][half * 2 + 0] * iv),
                    f2tf(acco[i][j][half * 2 + 1] * iv));
            }
        }
    }
}

// ===========================================================================
extern "C" void kernel_launch(void* const* d_in, const int* in_sizes, int n_in,
                              void* d_out, int out_size) {
    const float* x    = (const float*)d_in[0];
    const float* Wqkv = (const float*)d_in[1];
    const float* bqkv = (const float*)d_in[2];
    const float* Wo   = (const float*)d_in[3];
    const float* bo   = (const float*)d_in[4];

    float* y   = (float*)d_out;                         // [B,T,D]
    float* wts = (float*)d_out + (size_t)BT * D_MODEL;  // [B,H,T,T]

    const int GB_SMEM = 2 * 3 * 128 * GBS * 4;          // 110592
    const int SA_SMEM = SA_FLTS * 4;                    // ~174 KB
    const int AV_SMEM = AV_FLTS * 4;                    // ~83.5 KB
    cudaFuncSetAttribute(gemm_big<0>, cudaFuncAttributeMaxDynamicSharedMemorySize, GB_SMEM);
    cudaFuncSetAttribute(gemm_big<1>, cudaFuncAttributeMaxDynamicSharedMemorySize, GB_SMEM);
    cudaFuncSetAttribute(attn_scores_e, cudaFuncAttributeMaxDynamicSharedMemorySize, SA_SMEM);
    cudaFuncSetAttribute(attn_av,       cudaFuncAttributeMaxDynamicSharedMemorySize, AV_SMEM);

    float *wt_p = nullptr, *wot_p = nullptr, *ao_p = nullptr;
    cudaGetSymbolAddress((void**)&wt_p,  g_wt);
    cudaGetSymbolAddress((void**)&wot_p, g_wot);
    cudaGetSymbolAddress((void**)&ao_p,  g_ao);

    transpose_w2<<<dim3(96, 32, 2), dim3(32, 8)>>>(Wqkv, Wo, wt_p, wot_p);

    gemm_big<0><<<dim3(24, 32), 256, GB_SMEM>>>(x, wt_p, bqkv, nullptr);
    transpose_v<<<dim3(2, 64, 32), dim3(32, 8)>>>();

    attn_scores_e<<<dim3(16, 32), 256, SA_SMEM>>>(wts);
    attn_av<<<dim3(16, 32), 256, AV_SMEM>>>(wts);

    gemm_big<1><<<dim3(8, 32), 256, GB_SMEM>>>(ao_p, wot_p, bo, y);
}